// round 1
// baseline (speedup 1.0000x reference)
#include <cuda_runtime.h>
#include <math.h>

// Problem constants (fixed by the dataset)
#define NN 100000
#define EE 1000000

// ---------------- device scratch (no allocations allowed) ----------------
__device__ float g_h0[(size_t)NN * 128];        // encoder output      [N,128]
__device__ float g_h1[(size_t)NN * 256];        // layer1 output       [N,256]
__device__ float g_h2[(size_t)NN * 256];        // layer2 output       [N,256]
__device__ float g_h3[(size_t)NN * 128];        // layer3 output       [N,128]
__device__ float g_agg[(size_t)NN * 4 * 256];   // per-(dst,rel) sums  [N,R,dim]
__device__ float g_inv[(size_t)NN * 4];         // 1/max(cnt,1)        [N,R]
__device__ float g_pool[16 * 128];
__device__ float g_gcnt[16];

// ---------------- utility kernels ----------------
__global__ void k_zero(int which, long n) {
    float* p = (which == 0) ? g_agg : (which == 1) ? g_inv : (which == 2) ? g_pool : g_gcnt;
    long i = (long)blockIdx.x * blockDim.x + threadIdx.x;
    long st = (long)gridDim.x * blockDim.x;
    for (; i < n; i += st) p[i] = 0.f;
}

__global__ void k_zero_out(float* out, int n) {
    int i = blockIdx.x * blockDim.x + threadIdx.x;
    if (i < n) out[i] = 0.f;
}

// ---------------- edge-type counts (h-independent, once per call) ----------------
__global__ void k_count(const int* __restrict__ dst, const int* __restrict__ typ, int E) {
    int e = blockIdx.x * blockDim.x + threadIdx.x;
    if (e < E) atomicAdd(&g_inv[(size_t)dst[e] * 4 + typ[e]], 1.0f);
}

__global__ void k_invert(int n) {
    int i = blockIdx.x * blockDim.x + threadIdx.x;
    if (i < n) { float c = g_inv[i]; g_inv[i] = 1.0f / fmaxf(c, 1.0f); }
}

// ---------------- per-node-type encoder: h0[n,:] = x[n,:] @ W_nt[type[n]] ----------------
// One warp per node, float4 loads of W (hot in L2: 7 * 64KB).
__global__ void k_encoder(const float* __restrict__ x, const float* __restrict__ Wnt,
                          const int* __restrict__ nt, int N) {
    int warp = threadIdx.x >> 5, lane = threadIdx.x & 31;
    int n = blockIdx.x * 4 + warp;
    if (n >= N) return;
    __shared__ float xs[4][128];
    float4 xv = ((const float4*)(x + (size_t)n * 128))[lane];
    ((float4*)xs[warp])[lane] = xv;
    __syncwarp();
    const float4* W = (const float4*)(Wnt + (size_t)nt[n] * 16384);
    float4 acc = make_float4(0.f, 0.f, 0.f, 0.f);
#pragma unroll 8
    for (int k = 0; k < 128; k++) {
        float xk = xs[warp][k];
        float4 w = __ldg(&W[k * 32 + lane]);
        acc.x += xk * w.x; acc.y += xk * w.y; acc.z += xk * w.z; acc.w += xk * w.w;
    }
    ((float4*)(g_h0 + (size_t)n * 128))[lane] = acc;
}

// ---------------- edge scatter: agg[dst,rel,:] += h[src,:] (one warp per edge) ----------------
__global__ void k_scatter(const int* __restrict__ src, const int* __restrict__ dst,
                          const int* __restrict__ typ, int E, int dim, int layer) {
    const float* h = (layer == 1) ? g_h0 : (layer == 2) ? g_h1 : g_h2;
    int gt = blockIdx.x * blockDim.x + threadIdx.x;
    int e = gt >> 5, lane = gt & 31;
    if (e >= E) return;
    int s = src[e], d = dst[e], r = typ[e];
    const float4* hs = (const float4*)(h + (size_t)s * dim);
    float* a = g_agg + ((size_t)d * 4 + r) * dim;
    int nf4 = dim >> 2;
    for (int j = lane; j < nf4; j += 32) {
        float4 v = __ldg(&hs[j]);
        atomicAdd(a + 4 * j + 0, v.x);
        atomicAdd(a + 4 * j + 1, v.y);
        atomicAdd(a + 4 * j + 2, v.z);
        atomicAdd(a + 4 * j + 3, v.w);
    }
}

// ---------------- fused GEMM: out = [agg*inv | h] @ [Wr ; Ws] + b, optional relu ----------------
// 128x128 tile, BK=8, 256 threads, 8x8 per thread. A is virtual: agg (scaled by
// inv_cnt per (row, relation)) for k<K1, else the self-loop features h.
__global__ void k_gemm(const float* __restrict__ Wr, const float* __restrict__ Ws,
                       const float* __restrict__ bias, int layer, int M,
                       int dimshift, int Nout, int relu) {
    const float* hs = (layer == 1) ? g_h0 : (layer == 2) ? g_h1 : g_h2;
    float* out = (layer == 1) ? g_h1 : (layer == 2) ? g_h2 : g_h3;
    const int DIM = 1 << dimshift;
    const int K1 = DIM << 2;           // R * DIM
    const int Ktot = K1 + DIM;

    __shared__ float As[8][128];
    __shared__ float Bs[8][128];

    int tid = threadIdx.x;
    int tx = tid & 15, ty = tid >> 4;
    int row0 = blockIdx.x * 128;
    int col0 = blockIdx.y * 128;
    int a_r = tid >> 1;
    int a_c = (tid & 1) * 4;
    int b_r = tid >> 5;
    int b_c = (tid & 31) * 4;
    int arow = row0 + a_r;

    float acc[8][8];
#pragma unroll
    for (int i = 0; i < 8; i++)
#pragma unroll
        for (int j = 0; j < 8; j++) acc[i][j] = 0.f;

    for (int k0 = 0; k0 < Ktot; k0 += 8) {
        float4 av = make_float4(0.f, 0.f, 0.f, 0.f);
        if (arow < M) {
            int kk = k0 + a_c;
            if (kk < K1) {
                float ic = g_inv[(size_t)arow * 4 + (kk >> dimshift)];
                av = *(const float4*)(g_agg + (size_t)arow * K1 + kk);
                av.x *= ic; av.y *= ic; av.z *= ic; av.w *= ic;
            } else {
                av = *(const float4*)(hs + (size_t)arow * DIM + (kk - K1));
            }
        }
        As[a_c + 0][a_r] = av.x; As[a_c + 1][a_r] = av.y;
        As[a_c + 2][a_r] = av.z; As[a_c + 3][a_r] = av.w;
        {
            int kk = k0 + b_r;
            const float* bp = (kk < K1) ? (Wr + (size_t)kk * Nout)
                                        : (Ws + (size_t)(kk - K1) * Nout);
            float4 bv = *(const float4*)(bp + col0 + b_c);
            *(float4*)(&Bs[b_r][b_c]) = bv;
        }
        __syncthreads();
#pragma unroll
        for (int kk = 0; kk < 8; kk++) {
            float a[8], b[8];
            *(float4*)(a)     = *(const float4*)(&As[kk][ty * 8]);
            *(float4*)(a + 4) = *(const float4*)(&As[kk][ty * 8 + 4]);
            *(float4*)(b)     = *(const float4*)(&Bs[kk][tx * 8]);
            *(float4*)(b + 4) = *(const float4*)(&Bs[kk][tx * 8 + 4]);
#pragma unroll
            for (int i = 0; i < 8; i++)
#pragma unroll
                for (int j = 0; j < 8; j++)
                    acc[i][j] += a[i] * b[j];
        }
        __syncthreads();
    }

#pragma unroll
    for (int i = 0; i < 8; i++) {
        int r = row0 + ty * 8 + i;
        if (r >= M) continue;
#pragma unroll
        for (int j = 0; j < 8; j += 4) {
            int c = col0 + tx * 8 + j;
            float4 v;
            v.x = acc[i][j + 0] + bias[c + 0];
            v.y = acc[i][j + 1] + bias[c + 1];
            v.z = acc[i][j + 2] + bias[c + 2];
            v.w = acc[i][j + 3] + bias[c + 3];
            if (relu) {
                v.x = fmaxf(v.x, 0.f); v.y = fmaxf(v.y, 0.f);
                v.z = fmaxf(v.z, 0.f); v.w = fmaxf(v.w, 0.f);
            }
            *(float4*)(out + (size_t)r * Nout + c) = v;
        }
    }
}

// ---------------- graph pooling ----------------
__global__ void k_gcount(const int* __restrict__ gid, int N) {
    int n = blockIdx.x * blockDim.x + threadIdx.x;
    unsigned act = __ballot_sync(0xffffffff, n < N);
    if (n < N) {
        int g = gid[n];
        unsigned m = __match_any_sync(act, g);
        int leader = __ffs(m) - 1;
        if ((threadIdx.x & 31) == leader) atomicAdd(&g_gcnt[g], (float)__popc(m));
    }
}

__global__ void k_pool(const int* __restrict__ gid, int N) {
    int idx = blockIdx.x * blockDim.x + threadIdx.x;
    int n = idx >> 5, c = idx & 31;
    if (n >= N) return;
    int g = gid[n];
    float4 v = *(const float4*)(g_h3 + (size_t)n * 128 + c * 4);
    atomicAdd(&g_pool[g * 128 + c * 4 + 0], v.x);
    atomicAdd(&g_pool[g * 128 + c * 4 + 1], v.y);
    atomicAdd(&g_pool[g * 128 + c * 4 + 2], v.z);
    atomicAdd(&g_pool[g * 128 + c * 4 + 3], v.w);
}

// ---------------- finalize: emb = leaky_relu(pool/cnt); scores = sigmoid(emb@w+b) ----------------
__global__ void k_final(const float* __restrict__ wfc, const float* __restrict__ bfc,
                        float* __restrict__ out, int out_size) {
    __shared__ float emb[16 * 128];
    __shared__ float part[4];
    __shared__ float sc[16];
    int j = threadIdx.x;  // 128 threads
    for (int b = 0; b < 16; b++) {
        float c = fmaxf(g_gcnt[b], 1.0f);
        float v = g_pool[b * 128 + j] / c;
        v = (v >= 0.f) ? v : 0.01f * v;   // leaky_relu, default slope 0.01
        emb[b * 128 + j] = v;
    }
    float w = wfc[j];
    for (int b = 0; b < 16; b++) {
        float p = emb[b * 128 + j] * w;
        for (int off = 16; off; off >>= 1) p += __shfl_down_sync(0xffffffff, p, off);
        if ((j & 31) == 0) part[j >> 5] = p;
        __syncthreads();
        if (j == 0) {
            float s = part[0] + part[1] + part[2] + part[3] + bfc[0];
            sc[b] = 1.0f / (1.0f + expf(-s));
        }
        __syncthreads();
    }
    // Output layout (flattened pytree: scores, labels, methods, emb). Middle ints
    // are zeros (already zeroed). Place scores first, emb in the last 2048 slots.
    if (out_size >= 2064) {
        if (j < 16) out[j] = sc[j];
        int base = out_size - 2048;
        for (int b = 0; b < 16; b++) out[base + b * 128 + j] = emb[b * 128 + j];
    } else if (out_size >= 2048) {
        for (int b = 0; b < 16; b++) out[b * 128 + j] = emb[b * 128 + j];
    } else {
        if (j < 16 && j < out_size) out[j] = sc[j];
    }
}

// ---------------- launch ----------------
extern "C" void kernel_launch(void* const* d_in, const int* in_sizes, int n_in,
                              void* d_out, int out_size) {
    const float* x   = (const float*)d_in[0];
    const float* Wnt = (const float*)d_in[1];
    const float* Wr1 = (const float*)d_in[2];
    const float* Ws1 = (const float*)d_in[3];
    const float* b1  = (const float*)d_in[4];
    const float* Wr2 = (const float*)d_in[5];
    const float* Ws2 = (const float*)d_in[6];
    const float* b2  = (const float*)d_in[7];
    const float* Wr3 = (const float*)d_in[8];
    const float* Ws3 = (const float*)d_in[9];
    const float* b3  = (const float*)d_in[10];
    const float* wfc = (const float*)d_in[11];
    const float* bfc = (const float*)d_in[12];
    const int* esrc  = (const int*)d_in[13];
    const int* edst  = (const int*)d_in[14];
    const int* etyp  = (const int*)d_in[15];
    const int* ntyp  = (const int*)d_in[16];
    const int* gid   = (const int*)d_in[17];
    int N = in_sizes[16];  // node_type length
    int E = in_sizes[13];  // edge_src length

    // counts (h-independent)
    k_zero<<<2048, 256>>>(1, (long)N * 4);
    k_count<<<(E + 255) / 256, 256>>>(edst, etyp, E);
    k_invert<<<(N * 4 + 255) / 256, 256>>>(N * 4);

    // encoder
    k_encoder<<<(N + 3) / 4, 128>>>(x, Wnt, ntyp, N);

    dim3 gh((N + 127) / 128, 2);
    dim3 go((N + 127) / 128, 1);

    // layer 1 (dim=128 -> hidden 256, relu)
    k_zero<<<8192, 256>>>(0, (long)N * 4 * 128);
    k_scatter<<<(E * 32 + 255) / 256, 256>>>(esrc, edst, etyp, E, 128, 1);
    k_gemm<<<gh, 256>>>(Wr1, Ws1, b1, 1, N, 7, 256, 1);

    // layer 2 (dim=256 -> hidden 256, relu)
    k_zero<<<8192, 256>>>(0, (long)N * 4 * 256);
    k_scatter<<<(E * 32 + 255) / 256, 256>>>(esrc, edst, etyp, E, 256, 2);
    k_gemm<<<gh, 256>>>(Wr2, Ws2, b2, 2, N, 8, 256, 1);

    // layer 3 (dim=256 -> out 128, no relu)
    k_zero<<<8192, 256>>>(0, (long)N * 4 * 256);
    k_scatter<<<(E * 32 + 255) / 256, 256>>>(esrc, edst, etyp, E, 256, 3);
    k_gemm<<<go, 256>>>(Wr3, Ws3, b3, 3, N, 8, 128, 0);

    // pooling + head
    k_zero<<<16, 256>>>(2, 16 * 128);
    k_zero<<<1, 32>>>(3, 16);
    k_gcount<<<(N + 255) / 256, 256>>>(gid, N);
    k_pool<<<((N * 32) + 255) / 256, 256>>>(gid, N);
    k_zero_out<<<(out_size + 255) / 256, 256>>>((float*)d_out, out_size);
    k_final<<<1, 128>>>(wfc, bfc, (float*)d_out, out_size);
}

// round 2
// speedup vs baseline: 1.5728x; 1.5728x over previous
#include <cuda_runtime.h>
#include <math.h>

// Problem constants (fixed by the dataset)
#define NN 100000
#define EE 1000000
#define NRMAX (NN * 4)
#define NIDX_CAP 100992   // ceil((NN + 7*128)/128)*128

// ---------------- device scratch (no allocations allowed) ----------------
__device__ float g_h0[(size_t)NN * 128];        // encoder output      [N,128]
__device__ float g_h1[(size_t)NN * 256];        // layer1 output       [N,256]
__device__ float g_h2[(size_t)NN * 256];        // layer2 output       [N,256]
__device__ float g_h3[(size_t)NN * 128];        // layer3 output       [N,128]
__device__ float g_agg[(size_t)NN * 4 * 256];   // per-(dst,rel) means [N,R,dim]
__device__ float g_pool[16 * 128];
__device__ float g_gcnt[16];

__device__ int g_cnt[NRMAX];     // per-(dst,rel) edge counts
__device__ int g_off[NRMAX];     // exclusive offsets
__device__ int g_cur[NRMAX];     // bucket cursors
__device__ int g_bsum[1024];     // scan block sums
__device__ int g_eidx[EE];       // src ids grouped by (dst,rel)
__device__ int g_nt_cnt[8];
__device__ int g_nt_off[8];
__device__ int g_nt_cur[8];
__device__ int g_nidx[NIDX_CAP]; // nodes grouped by type, 128-padded, -1 = hole

// ---------------- small utility kernels ----------------
__global__ void k_zero_i32(int which, int n) {
    int* p = (which == 0) ? g_cnt : g_nt_cnt;
    int i = blockIdx.x * blockDim.x + threadIdx.x;
    if (i < n) p[i] = 0;
}
__global__ void k_fill_nidx() {
    int i = blockIdx.x * blockDim.x + threadIdx.x;
    if (i < NIDX_CAP) g_nidx[i] = -1;
}
__global__ void k_zero_pool() {
    int i = blockIdx.x * blockDim.x + threadIdx.x;
    if (i < 2048) g_pool[i] = 0.f;
    if (i < 16) g_gcnt[i] = 0.f;
}
__global__ void k_zero_out(float* out, int n) {
    int i = blockIdx.x * blockDim.x + threadIdx.x;
    if (i < n) out[i] = 0.f;
}

// ---------------- edge CSR build (counting sort by (dst,rel)) ----------------
__global__ void k_hist(const int* __restrict__ dst, const int* __restrict__ typ, int E) {
    int e = blockIdx.x * blockDim.x + threadIdx.x;
    if (e < E) atomicAdd(&g_cnt[dst[e] * 4 + typ[e]], 1);
}

__device__ __forceinline__ int block_scan_incl(int v, int* ws) {
    int lane = threadIdx.x & 31, wid = threadIdx.x >> 5;
#pragma unroll
    for (int o = 1; o < 32; o <<= 1) {
        int t = __shfl_up_sync(0xffffffffu, v, o);
        if (lane >= o) v += t;
    }
    if (lane == 31) ws[wid] = v;
    __syncthreads();
    if (wid == 0) {
        int w = (lane < (int)(blockDim.x >> 5)) ? ws[lane] : 0;
#pragma unroll
        for (int o = 1; o < 32; o <<= 1) {
            int t = __shfl_up_sync(0xffffffffu, w, o);
            if (lane >= o) w += t;
        }
        ws[lane] = w;
    }
    __syncthreads();
    return v + (wid > 0 ? ws[wid - 1] : 0);
}

__global__ void k_scan1(int n) {
    __shared__ int ws[32];
    int i = blockIdx.x * 1024 + threadIdx.x;
    int c = (i < n) ? g_cnt[i] : 0;
    int incl = block_scan_incl(c, ws);
    if (i < n) g_off[i] = incl - c;
    if (threadIdx.x == 1023) g_bsum[blockIdx.x] = incl;
}
__global__ void k_scan2(int nb) {
    __shared__ int ws[32];
    int i = threadIdx.x;
    int v = (i < nb) ? g_bsum[i] : 0;
    int incl = block_scan_incl(v, ws);
    if (i < nb) g_bsum[i] = incl - v;
}
__global__ void k_scan3(int n) {
    int i = blockIdx.x * 1024 + threadIdx.x;
    if (i < n) {
        int o = g_off[i] + g_bsum[i >> 10];
        g_off[i] = o;
        g_cur[i] = o;
    }
}
__global__ void k_bucket(const int* __restrict__ src, const int* __restrict__ dst,
                         const int* __restrict__ typ, int E) {
    int e = blockIdx.x * blockDim.x + threadIdx.x;
    if (e < E) {
        int key = dst[e] * 4 + typ[e];
        int pos = atomicAdd(&g_cur[key], 1);
        g_eidx[pos] = src[e];
    }
}

// ---------------- node-type counting sort (7 bins, 128-padded) ----------------
__global__ void k_hist_nt(const int* __restrict__ nt, int N) {
    int n = blockIdx.x * blockDim.x + threadIdx.x;
    unsigned act = __ballot_sync(0xffffffffu, n < N);
    if (n < N) {
        int t = nt[n];
        unsigned m = __match_any_sync(act, t);
        if ((threadIdx.x & 31) == __ffs(m) - 1) atomicAdd(&g_nt_cnt[t], __popc(m));
    }
}
__global__ void k_nt_offsets() {
    if (threadIdx.x == 0) {
        int off = 0;
        for (int t = 0; t < 7; t++) {
            g_nt_off[t] = off;
            g_nt_cur[t] = off;
            off += ((g_nt_cnt[t] + 127) / 128) * 128;
        }
        g_nt_off[7] = off;
    }
}
__global__ void k_bucket_nt(const int* __restrict__ nt, int N) {
    int n = blockIdx.x * blockDim.x + threadIdx.x;
    unsigned act = __ballot_sync(0xffffffffu, n < N);
    if (n < N) {
        int t = nt[n];
        unsigned m = __match_any_sync(act, t);
        int leader = __ffs(m) - 1;
        unsigned lt = (1u << (threadIdx.x & 31)) - 1u;
        int rank = __popc(m & lt);
        int base = 0;
        if ((threadIdx.x & 31) == leader) base = atomicAdd(&g_nt_cur[t], __popc(m));
        base = __shfl_sync(act, base, leader);
        g_nidx[base + rank] = n;
    }
}

// ---------------- encoder as gather-GEMM: h0[n] = x[n] @ W_nt[type[n]] ----------------
// 128x128 tile over type-sorted node list; W loaded once per tile.
__global__ void k_enc_gemm(const float* __restrict__ x, const float* __restrict__ Wnt) {
    __shared__ float As[8][128];
    __shared__ float Bs[8][128];
    int base = blockIdx.x * 128;
    if (base >= g_nt_off[7]) return;
    int t = 0;
    while (t < 6 && base >= g_nt_off[t + 1]) t++;
    const float* W = Wnt + (size_t)t * 16384;

    int tid = threadIdx.x;
    int tx = tid & 15, ty = tid >> 4;
    int a_r = tid >> 1, a_c = (tid & 1) * 4;
    int b_r = tid >> 5, b_c = (tid & 31) * 4;
    int anode = g_nidx[base + a_r];

    float acc[8][8];
#pragma unroll
    for (int i = 0; i < 8; i++)
#pragma unroll
        for (int j = 0; j < 8; j++) acc[i][j] = 0.f;

    for (int k0 = 0; k0 < 128; k0 += 8) {
        float4 av = make_float4(0.f, 0.f, 0.f, 0.f);
        if (anode >= 0) av = *(const float4*)(x + (size_t)anode * 128 + k0 + a_c);
        As[a_c + 0][a_r] = av.x; As[a_c + 1][a_r] = av.y;
        As[a_c + 2][a_r] = av.z; As[a_c + 3][a_r] = av.w;
        *(float4*)(&Bs[b_r][b_c]) = *(const float4*)(W + (size_t)(k0 + b_r) * 128 + b_c);
        __syncthreads();
#pragma unroll
        for (int kk = 0; kk < 8; kk++) {
            float a[8], b[8];
            *(float4*)(a)     = *(const float4*)(&As[kk][ty * 8]);
            *(float4*)(a + 4) = *(const float4*)(&As[kk][ty * 8 + 4]);
            *(float4*)(b)     = *(const float4*)(&Bs[kk][tx * 8]);
            *(float4*)(b + 4) = *(const float4*)(&Bs[kk][tx * 8 + 4]);
#pragma unroll
            for (int i = 0; i < 8; i++)
#pragma unroll
                for (int j = 0; j < 8; j++)
                    acc[i][j] += a[i] * b[j];
        }
        __syncthreads();
    }
#pragma unroll
    for (int i = 0; i < 8; i++) {
        int node = g_nidx[base + ty * 8 + i];
        if (node < 0) continue;
#pragma unroll
        for (int j = 0; j < 8; j += 4) {
            float4 v = make_float4(acc[i][j], acc[i][j + 1], acc[i][j + 2], acc[i][j + 3]);
            *(float4*)(g_h0 + (size_t)node * 128 + tx * 8 + j) = v;
        }
    }
}

// ---------------- grouped aggregation: agg[n,r,:] = mean_{e in seg(n,r)} h[src_e,:] ----------------
// 64-thread group per node, fully coalesced gather, plain stores (no atomics).
template <int DIM>
__global__ void k_agg(int layer, int N) {
    const float* __restrict__ h = (layer == 1) ? g_h0 : (layer == 2) ? g_h1 : g_h2;
    int node = blockIdx.x * 4 + (threadIdx.x >> 6);
    if (node >= N) return;
    int gl = threadIdx.x & 63;
    const int V = DIM / 64;  // 2 or 4 floats per thread
    float* outbase = g_agg + (size_t)node * 4 * DIM + gl * V;
#pragma unroll
    for (int r = 0; r < 4; r++) {
        int key = node * 4 + r;
        int beg = g_off[key];
        int c = g_cnt[key];
        float a0 = 0.f, a1 = 0.f, a2 = 0.f, a3 = 0.f;
        int s = (c > 0) ? g_eidx[beg] : 0;
        for (int k = 0; k < c; k++) {
            int snext = (k + 1 < c) ? g_eidx[beg + k + 1] : 0;
            const float* row = h + (size_t)s * DIM + gl * V;
            if (V == 4) {
                float4 v = *(const float4*)row;
                a0 += v.x; a1 += v.y; a2 += v.z; a3 += v.w;
            } else {
                float2 v = *(const float2*)row;
                a0 += v.x; a1 += v.y;
            }
            s = snext;
        }
        float inv = 1.0f / fmaxf((float)c, 1.0f);
        float* o = outbase + r * DIM;
        if (V == 4) *(float4*)o = make_float4(a0 * inv, a1 * inv, a2 * inv, a3 * inv);
        else        *(float2*)o = make_float2(a0 * inv, a1 * inv);
    }
}

// ---------------- fused GEMM: out = [mean | h] @ [Wr ; Ws] + b, optional relu ----------------
__global__ void k_gemm(const float* __restrict__ Wr, const float* __restrict__ Ws,
                       const float* __restrict__ bias, int layer, int M,
                       int dimshift, int Nout, int relu) {
    const float* hs = (layer == 1) ? g_h0 : (layer == 2) ? g_h1 : g_h2;
    float* out = (layer == 1) ? g_h1 : (layer == 2) ? g_h2 : g_h3;
    const int DIM = 1 << dimshift;
    const int K1 = DIM << 2;           // R * DIM
    const int Ktot = K1 + DIM;

    __shared__ float As[8][128];
    __shared__ float Bs[8][128];

    int tid = threadIdx.x;
    int tx = tid & 15, ty = tid >> 4;
    int row0 = blockIdx.x * 128;
    int col0 = blockIdx.y * 128;
    int a_r = tid >> 1;
    int a_c = (tid & 1) * 4;
    int b_r = tid >> 5;
    int b_c = (tid & 31) * 4;
    int arow = row0 + a_r;

    float acc[8][8];
#pragma unroll
    for (int i = 0; i < 8; i++)
#pragma unroll
        for (int j = 0; j < 8; j++) acc[i][j] = 0.f;

    for (int k0 = 0; k0 < Ktot; k0 += 8) {
        float4 av = make_float4(0.f, 0.f, 0.f, 0.f);
        if (arow < M) {
            int kk = k0 + a_c;
            if (kk < K1) av = *(const float4*)(g_agg + (size_t)arow * K1 + kk);
            else         av = *(const float4*)(hs + (size_t)arow * DIM + (kk - K1));
        }
        As[a_c + 0][a_r] = av.x; As[a_c + 1][a_r] = av.y;
        As[a_c + 2][a_r] = av.z; As[a_c + 3][a_r] = av.w;
        {
            int kk = k0 + b_r;
            const float* bp = (kk < K1) ? (Wr + (size_t)kk * Nout)
                                        : (Ws + (size_t)(kk - K1) * Nout);
            *(float4*)(&Bs[b_r][b_c]) = *(const float4*)(bp + col0 + b_c);
        }
        __syncthreads();
#pragma unroll
        for (int kk = 0; kk < 8; kk++) {
            float a[8], b[8];
            *(float4*)(a)     = *(const float4*)(&As[kk][ty * 8]);
            *(float4*)(a + 4) = *(const float4*)(&As[kk][ty * 8 + 4]);
            *(float4*)(b)     = *(const float4*)(&Bs[kk][tx * 8]);
            *(float4*)(b + 4) = *(const float4*)(&Bs[kk][tx * 8 + 4]);
#pragma unroll
            for (int i = 0; i < 8; i++)
#pragma unroll
                for (int j = 0; j < 8; j++)
                    acc[i][j] += a[i] * b[j];
        }
        __syncthreads();
    }

#pragma unroll
    for (int i = 0; i < 8; i++) {
        int r = row0 + ty * 8 + i;
        if (r >= M) continue;
#pragma unroll
        for (int j = 0; j < 8; j += 4) {
            int c = col0 + tx * 8 + j;
            float4 v;
            v.x = acc[i][j + 0] + bias[c + 0];
            v.y = acc[i][j + 1] + bias[c + 1];
            v.z = acc[i][j + 2] + bias[c + 2];
            v.w = acc[i][j + 3] + bias[c + 3];
            if (relu) {
                v.x = fmaxf(v.x, 0.f); v.y = fmaxf(v.y, 0.f);
                v.z = fmaxf(v.z, 0.f); v.w = fmaxf(v.w, 0.f);
            }
            *(float4*)(out + (size_t)r * Nout + c) = v;
        }
    }
}

// ---------------- graph pooling ----------------
__global__ void k_gcount(const int* __restrict__ gid, int N) {
    int n = blockIdx.x * blockDim.x + threadIdx.x;
    unsigned act = __ballot_sync(0xffffffffu, n < N);
    if (n < N) {
        int g = gid[n];
        unsigned m = __match_any_sync(act, g);
        if ((threadIdx.x & 31) == __ffs(m) - 1) atomicAdd(&g_gcnt[g], (float)__popc(m));
    }
}

// graph_id is sorted: accumulate runs locally, flush per run change.
__global__ void k_pool(const int* __restrict__ gid, int N) {
    int j = threadIdx.x;          // 128 threads, one per column
    int n0 = blockIdx.x * 64;
    if (n0 >= N) return;
    int nend = min(n0 + 64, N);
    int curg = gid[n0];
    float acc = 0.f;
    for (int n = n0; n < nend; n++) {
        int g = gid[n];
        if (g != curg) {
            atomicAdd(&g_pool[curg * 128 + j], acc);
            acc = 0.f;
            curg = g;
        }
        acc += g_h3[(size_t)n * 128 + j];
    }
    atomicAdd(&g_pool[curg * 128 + j], acc);
}

// ---------------- finalize ----------------
__global__ void k_final(const float* __restrict__ wfc, const float* __restrict__ bfc,
                        float* __restrict__ out, int out_size) {
    __shared__ float emb[16 * 128];
    __shared__ float part[4];
    __shared__ float sc[16];
    int j = threadIdx.x;  // 128 threads
    for (int b = 0; b < 16; b++) {
        float c = fmaxf(g_gcnt[b], 1.0f);
        float v = g_pool[b * 128 + j] / c;
        v = (v >= 0.f) ? v : 0.01f * v;   // leaky_relu
        emb[b * 128 + j] = v;
    }
    float w = wfc[j];
    for (int b = 0; b < 16; b++) {
        float p = emb[b * 128 + j] * w;
        for (int off = 16; off; off >>= 1) p += __shfl_down_sync(0xffffffffu, p, off);
        if ((j & 31) == 0) part[j >> 5] = p;
        __syncthreads();
        if (j == 0) {
            float s = part[0] + part[1] + part[2] + part[3] + bfc[0];
            sc[b] = 1.0f / (1.0f + expf(-s));
        }
        __syncthreads();
    }
    if (out_size >= 2064) {
        if (j < 16) out[j] = sc[j];
        int base = out_size - 2048;
        for (int b = 0; b < 16; b++) out[base + b * 128 + j] = emb[b * 128 + j];
    } else if (out_size >= 2048) {
        for (int b = 0; b < 16; b++) out[b * 128 + j] = emb[b * 128 + j];
    } else {
        if (j < 16 && j < out_size) out[j] = sc[j];
    }
}

// ---------------- launch ----------------
extern "C" void kernel_launch(void* const* d_in, const int* in_sizes, int n_in,
                              void* d_out, int out_size) {
    const float* x   = (const float*)d_in[0];
    const float* Wnt = (const float*)d_in[1];
    const float* Wr1 = (const float*)d_in[2];
    const float* Ws1 = (const float*)d_in[3];
    const float* b1  = (const float*)d_in[4];
    const float* Wr2 = (const float*)d_in[5];
    const float* Ws2 = (const float*)d_in[6];
    const float* b2  = (const float*)d_in[7];
    const float* Wr3 = (const float*)d_in[8];
    const float* Ws3 = (const float*)d_in[9];
    const float* b3  = (const float*)d_in[10];
    const float* wfc = (const float*)d_in[11];
    const float* bfc = (const float*)d_in[12];
    const int* esrc  = (const int*)d_in[13];
    const int* edst  = (const int*)d_in[14];
    const int* etyp  = (const int*)d_in[15];
    const int* ntyp  = (const int*)d_in[16];
    const int* gid   = (const int*)d_in[17];
    int N = in_sizes[16];
    int E = in_sizes[13];
    int NR = N * 4;
    int NB = (NR + 1023) / 1024;

    // edge CSR build
    k_zero_i32<<<(NR + 255) / 256, 256>>>(0, NR);
    k_hist<<<(E + 255) / 256, 256>>>(edst, etyp, E);
    k_scan1<<<NB, 1024>>>(NR);
    k_scan2<<<1, 1024>>>(NB);
    k_scan3<<<NB, 1024>>>(NR);
    k_bucket<<<(E + 255) / 256, 256>>>(esrc, edst, etyp, E);

    // node-type sort + encoder GEMM
    k_zero_i32<<<1, 32>>>(1, 8);
    k_fill_nidx<<<(NIDX_CAP + 255) / 256, 256>>>();
    k_hist_nt<<<(N + 255) / 256, 256>>>(ntyp, N);
    k_nt_offsets<<<1, 32>>>();
    k_bucket_nt<<<(N + 255) / 256, 256>>>(ntyp, N);
    int gx_enc = (N + 7 * 128 + 127) / 128;
    k_enc_gemm<<<gx_enc, 256>>>(x, Wnt);

    int gagg = (N + 3) / 4;
    dim3 gh((N + 127) / 128, 2);
    dim3 go((N + 127) / 128, 1);

    // layer 1 (128 -> 256, relu)
    k_agg<128><<<gagg, 256>>>(1, N);
    k_gemm<<<gh, 256>>>(Wr1, Ws1, b1, 1, N, 7, 256, 1);

    // layer 2 (256 -> 256, relu)
    k_agg<256><<<gagg, 256>>>(2, N);
    k_gemm<<<gh, 256>>>(Wr2, Ws2, b2, 2, N, 8, 256, 1);

    // layer 3 (256 -> 128, no relu)
    k_agg<256><<<gagg, 256>>>(3, N);
    k_gemm<<<go, 256>>>(Wr3, Ws3, b3, 3, N, 8, 128, 0);

    // pooling + head
    k_zero_pool<<<8, 256>>>();
    k_gcount<<<(N + 255) / 256, 256>>>(gid, N);
    k_pool<<<(N + 63) / 64, 128>>>(gid, N);
    k_zero_out<<<(out_size + 255) / 256, 256>>>((float*)d_out, out_size);
    k_final<<<1, 128>>>(wfc, bfc, (float*)d_out, out_size);
}

// round 3
// speedup vs baseline: 3.9745x; 2.5270x over previous
#include <cuda_runtime.h>
#include <math.h>

// Problem constants (fixed by the dataset)
#define NN 100000
#define EE 1000000
#define NRMAX (NN * 4)
#define NIDX_CAP 100992   // ceil((NN + 7*128)/128)*128

// ---------------- device scratch (no allocations allowed) ----------------
__device__ float g_h0[(size_t)NN * 128];        // encoder output      [N,128]
__device__ float g_h1[(size_t)NN * 256];        // layer1 output       [N,256]
__device__ float g_h2[(size_t)NN * 256];        // layer2 output       [N,256]
__device__ float g_h3[(size_t)NN * 128];        // layer3 output       [N,128]
__device__ float g_agg[(size_t)NN * 4 * 256];   // per-(dst,rel) means [N,R,dim]
__device__ float g_pool[16 * 128];
__device__ float g_gcnt[16];

__device__ int g_cnt[NRMAX];     // per-(dst,rel) edge counts
__device__ int g_off[NRMAX];     // exclusive offsets
__device__ int g_cur[NRMAX];     // bucket cursors
__device__ int g_bsum[1024];     // scan block sums
__device__ int g_eidx[EE];       // src ids grouped by (dst,rel)
__device__ int g_nt_cnt[8];
__device__ int g_nt_off[8];
__device__ int g_nt_cur[8];
__device__ int g_nidx[NIDX_CAP]; // nodes grouped by type, 128-padded, -1 = hole

// ---------------- small utility kernels ----------------
__global__ void k_zero_i32(int which, int n) {
    int* p = (which == 0) ? g_cnt : g_nt_cnt;
    int i = blockIdx.x * blockDim.x + threadIdx.x;
    if (i < n) p[i] = 0;
}
__global__ void k_fill_nidx() {
    int i = blockIdx.x * blockDim.x + threadIdx.x;
    if (i < NIDX_CAP) g_nidx[i] = -1;
}
__global__ void k_zero_pool() {
    int i = blockIdx.x * blockDim.x + threadIdx.x;
    if (i < 2048) g_pool[i] = 0.f;
    if (i < 16) g_gcnt[i] = 0.f;
}
__global__ void k_zero_out(float* out, int n) {
    int i = blockIdx.x * blockDim.x + threadIdx.x;
    if (i < n) out[i] = 0.f;
}

// ---------------- edge CSR build (counting sort by (dst,rel)) ----------------
__global__ void k_hist(const int* __restrict__ dst, const int* __restrict__ typ, int E) {
    int e = blockIdx.x * blockDim.x + threadIdx.x;
    if (e < E) atomicAdd(&g_cnt[dst[e] * 4 + typ[e]], 1);
}

__device__ __forceinline__ int block_scan_incl(int v, int* ws) {
    int lane = threadIdx.x & 31, wid = threadIdx.x >> 5;
#pragma unroll
    for (int o = 1; o < 32; o <<= 1) {
        int t = __shfl_up_sync(0xffffffffu, v, o);
        if (lane >= o) v += t;
    }
    if (lane == 31) ws[wid] = v;
    __syncthreads();
    if (wid == 0) {
        int w = (lane < (int)(blockDim.x >> 5)) ? ws[lane] : 0;
#pragma unroll
        for (int o = 1; o < 32; o <<= 1) {
            int t = __shfl_up_sync(0xffffffffu, w, o);
            if (lane >= o) w += t;
        }
        ws[lane] = w;
    }
    __syncthreads();
    return v + (wid > 0 ? ws[wid - 1] : 0);
}

__global__ void k_scan1(int n) {
    __shared__ int ws[32];
    int i = blockIdx.x * 1024 + threadIdx.x;
    int c = (i < n) ? g_cnt[i] : 0;
    int incl = block_scan_incl(c, ws);
    if (i < n) g_off[i] = incl - c;
    if (threadIdx.x == 1023) g_bsum[blockIdx.x] = incl;
}
__global__ void k_scan2(int nb) {
    __shared__ int ws[32];
    int i = threadIdx.x;
    int v = (i < nb) ? g_bsum[i] : 0;
    int incl = block_scan_incl(v, ws);
    if (i < nb) g_bsum[i] = incl - v;
}
__global__ void k_scan3(int n) {
    int i = blockIdx.x * 1024 + threadIdx.x;
    if (i < n) {
        int o = g_off[i] + g_bsum[i >> 10];
        g_off[i] = o;
        g_cur[i] = o;
    }
}
__global__ void k_bucket(const int* __restrict__ src, const int* __restrict__ dst,
                         const int* __restrict__ typ, int E) {
    int e = blockIdx.x * blockDim.x + threadIdx.x;
    if (e < E) {
        int key = dst[e] * 4 + typ[e];
        int pos = atomicAdd(&g_cur[key], 1);
        g_eidx[pos] = src[e];
    }
}

// ---------------- node-type counting sort (7 bins, 128-padded) ----------------
__global__ void k_hist_nt(const int* __restrict__ nt, int N) {
    int n = blockIdx.x * blockDim.x + threadIdx.x;
    unsigned act = __ballot_sync(0xffffffffu, n < N);
    if (n < N) {
        int t = nt[n];
        unsigned m = __match_any_sync(act, t);
        if ((threadIdx.x & 31) == __ffs(m) - 1) atomicAdd(&g_nt_cnt[t], __popc(m));
    }
}
__global__ void k_nt_offsets() {
    if (threadIdx.x == 0) {
        int off = 0;
        for (int t = 0; t < 7; t++) {
            g_nt_off[t] = off;
            g_nt_cur[t] = off;
            off += ((g_nt_cnt[t] + 127) / 128) * 128;
        }
        g_nt_off[7] = off;
    }
}
__global__ void k_bucket_nt(const int* __restrict__ nt, int N) {
    int n = blockIdx.x * blockDim.x + threadIdx.x;
    unsigned act = __ballot_sync(0xffffffffu, n < N);
    if (n < N) {
        int t = nt[n];
        unsigned m = __match_any_sync(act, t);
        int leader = __ffs(m) - 1;
        unsigned lt = (1u << (threadIdx.x & 31)) - 1u;
        int rank = __popc(m & lt);
        int base = 0;
        if ((threadIdx.x & 31) == leader) base = atomicAdd(&g_nt_cur[t], __popc(m));
        base = __shfl_sync(act, base, leader);
        g_nidx[base + rank] = n;
    }
}

// ---------------- encoder as gather-GEMM: h0[n] = x[n] @ W_nt[type[n]] ----------------
__global__ void k_enc_gemm(const float* __restrict__ x, const float* __restrict__ Wnt) {
    __shared__ float As[8][128];
    __shared__ float Bs[8][128];
    int base = blockIdx.x * 128;
    if (base >= g_nt_off[7]) return;
    int t = 0;
    while (t < 6 && base >= g_nt_off[t + 1]) t++;
    const float* W = Wnt + (size_t)t * 16384;

    int tid = threadIdx.x;
    int tx = tid & 15, ty = tid >> 4;
    int a_r = tid >> 1, a_c = (tid & 1) * 4;
    int b_r = tid >> 5, b_c = (tid & 31) * 4;
    int anode = g_nidx[base + a_r];

    float acc[8][8];
#pragma unroll
    for (int i = 0; i < 8; i++)
#pragma unroll
        for (int j = 0; j < 8; j++) acc[i][j] = 0.f;

    for (int k0 = 0; k0 < 128; k0 += 8) {
        float4 av = make_float4(0.f, 0.f, 0.f, 0.f);
        if (anode >= 0) av = *(const float4*)(x + (size_t)anode * 128 + k0 + a_c);
        As[a_c + 0][a_r] = av.x; As[a_c + 1][a_r] = av.y;
        As[a_c + 2][a_r] = av.z; As[a_c + 3][a_r] = av.w;
        *(float4*)(&Bs[b_r][b_c]) = *(const float4*)(W + (size_t)(k0 + b_r) * 128 + b_c);
        __syncthreads();
#pragma unroll
        for (int kk = 0; kk < 8; kk++) {
            float a[8], b[8];
            *(float4*)(a)     = *(const float4*)(&As[kk][ty * 8]);
            *(float4*)(a + 4) = *(const float4*)(&As[kk][ty * 8 + 4]);
            *(float4*)(b)     = *(const float4*)(&Bs[kk][tx * 8]);
            *(float4*)(b + 4) = *(const float4*)(&Bs[kk][tx * 8 + 4]);
#pragma unroll
            for (int i = 0; i < 8; i++)
#pragma unroll
                for (int j = 0; j < 8; j++)
                    acc[i][j] += a[i] * b[j];
        }
        __syncthreads();
    }
#pragma unroll
    for (int i = 0; i < 8; i++) {
        int node = g_nidx[base + ty * 8 + i];
        if (node < 0) continue;
#pragma unroll
        for (int j = 0; j < 8; j += 4) {
            float4 v = make_float4(acc[i][j], acc[i][j + 1], acc[i][j + 2], acc[i][j + 3]);
            *(float4*)(g_h0 + (size_t)node * 128 + tx * 8 + j) = v;
        }
    }
}

// ---------------- grouped aggregation: agg[n,r,:] = mean over CSR segment ----------------
template <int DIM>
__global__ void k_agg(int layer, int N) {
    const float* __restrict__ h = (layer == 1) ? g_h0 : (layer == 2) ? g_h1 : g_h2;
    int node = blockIdx.x * 4 + (threadIdx.x >> 6);
    if (node >= N) return;
    int gl = threadIdx.x & 63;
    const int V = DIM / 64;
    float* outbase = g_agg + (size_t)node * 4 * DIM + gl * V;
#pragma unroll
    for (int r = 0; r < 4; r++) {
        int key = node * 4 + r;
        int beg = g_off[key];
        int c = g_cnt[key];
        float a0 = 0.f, a1 = 0.f, a2 = 0.f, a3 = 0.f;
        int s = (c > 0) ? g_eidx[beg] : 0;
        for (int k = 0; k < c; k++) {
            int snext = (k + 1 < c) ? g_eidx[beg + k + 1] : 0;
            const float* row = h + (size_t)s * DIM + gl * V;
            if (V == 4) {
                float4 v = *(const float4*)row;
                a0 += v.x; a1 += v.y; a2 += v.z; a3 += v.w;
            } else {
                float2 v = *(const float2*)row;
                a0 += v.x; a1 += v.y;
            }
            s = snext;
        }
        float inv = 1.0f / fmaxf((float)c, 1.0f);
        float* o = outbase + r * DIM;
        if (V == 4) *(float4*)o = make_float4(a0 * inv, a1 * inv, a2 * inv, a3 * inv);
        else        *(float2*)o = make_float2(a0 * inv, a1 * inv);
    }
}

// ---------------- tf32 tensor-core GEMM: out = [mean | h] @ [Wr ; Ws] + b ----------------
// 128x128x16 tiles, 8 warps x (64x32), m16n8k8 tf32 mma, double-buffered smem.
__device__ __forceinline__ unsigned f2tf32(float x) {
    unsigned r;
    asm("cvt.rna.tf32.f32 %0, %1;" : "=r"(r) : "f"(x));
    return r;
}

__global__ void __launch_bounds__(256) k_gemm_tc(
        const float* __restrict__ Wr, const float* __restrict__ Ws,
        const float* __restrict__ bias, int layer, int M,
        int dimshift, int Nout, int relu) {
    const float* __restrict__ hs = (layer == 1) ? g_h0 : (layer == 2) ? g_h1 : g_h2;
    float* __restrict__ out = (layer == 1) ? g_h1 : (layer == 2) ? g_h2 : g_h3;
    const int DIM = 1 << dimshift;
    const int K1 = DIM << 2;
    const int Ktot = K1 + DIM;

    __shared__ float As[2][128][20];   // [buf][m][k] (k padded 16->20: conflict-free quads)
    __shared__ float Bs[2][16][136];   // [buf][k][n] (n padded 128->136)

    int tid = threadIdx.x;
    int lane = tid & 31, warp = tid >> 5;
    int wm = (warp >> 2) * 64;         // warp row offset (0/64)
    int wn = (warp & 3) * 32;          // warp col offset (0/32/64/96)
    int row0 = blockIdx.x * 128, col0 = blockIdx.y * 128;

    int ar = tid >> 1;                 // A row 0..127
    int ac = (tid & 1) * 8;            // A col 0 or 8
    int arow = row0 + ar;
    bool avalid = arow < M;
    int br = tid >> 4;                 // B k-row 0..15
    int bc = (tid & 15) * 8;           // B col

    float acc[4][4][4];
#pragma unroll
    for (int i = 0; i < 4; i++)
#pragma unroll
        for (int j = 0; j < 4; j++)
#pragma unroll
            for (int q = 0; q < 4; q++) acc[i][j][q] = 0.f;

    float4 ra0, ra1, rb0, rb1;

    auto fetch = [&](int k0) {
        ra0 = make_float4(0.f, 0.f, 0.f, 0.f);
        ra1 = ra0;
        if (avalid) {
            const float* p = (k0 < K1)
                ? (g_agg + (size_t)arow * K1 + k0 + ac)
                : (hs + (size_t)arow * DIM + (k0 - K1) + ac);
            ra0 = *(const float4*)p;
            ra1 = *(const float4*)(p + 4);
        }
        int kk = k0 + br;
        const float* bp = (kk < K1) ? (Wr + (size_t)kk * Nout)
                                    : (Ws + (size_t)(kk - K1) * Nout);
        bp += col0 + bc;
        rb0 = *(const float4*)bp;
        rb1 = *(const float4*)(bp + 4);
    };

    auto stage = [&](int buf) {
        float* a = &As[buf][ar][ac];
        a[0] = __uint_as_float(f2tf32(ra0.x)); a[1] = __uint_as_float(f2tf32(ra0.y));
        a[2] = __uint_as_float(f2tf32(ra0.z)); a[3] = __uint_as_float(f2tf32(ra0.w));
        a[4] = __uint_as_float(f2tf32(ra1.x)); a[5] = __uint_as_float(f2tf32(ra1.y));
        a[6] = __uint_as_float(f2tf32(ra1.z)); a[7] = __uint_as_float(f2tf32(ra1.w));
        float* b = &Bs[buf][br][bc];
        b[0] = __uint_as_float(f2tf32(rb0.x)); b[1] = __uint_as_float(f2tf32(rb0.y));
        b[2] = __uint_as_float(f2tf32(rb0.z)); b[3] = __uint_as_float(f2tf32(rb0.w));
        b[4] = __uint_as_float(f2tf32(rb1.x)); b[5] = __uint_as_float(f2tf32(rb1.y));
        b[6] = __uint_as_float(f2tf32(rb1.z)); b[7] = __uint_as_float(f2tf32(rb1.w));
    };

    int lr = lane >> 2;   // 0..7
    int lc = lane & 3;    // 0..3

    auto compute = [&](int buf) {
#pragma unroll
        for (int ks = 0; ks < 2; ks++) {
            int kk = ks * 8;
            unsigned af[4][4], bf[4][2];
#pragma unroll
            for (int mt = 0; mt < 4; mt++) {
                int r = wm + mt * 16 + lr;
                af[mt][0] = __float_as_uint(As[buf][r][kk + lc]);
                af[mt][1] = __float_as_uint(As[buf][r + 8][kk + lc]);
                af[mt][2] = __float_as_uint(As[buf][r][kk + lc + 4]);
                af[mt][3] = __float_as_uint(As[buf][r + 8][kk + lc + 4]);
            }
#pragma unroll
            for (int nt = 0; nt < 4; nt++) {
                int n = wn + nt * 8 + lr;
                bf[nt][0] = __float_as_uint(Bs[buf][kk + lc][n]);
                bf[nt][1] = __float_as_uint(Bs[buf][kk + lc + 4][n]);
            }
#pragma unroll
            for (int mt = 0; mt < 4; mt++)
#pragma unroll
                for (int nt = 0; nt < 4; nt++) {
                    asm volatile(
                        "mma.sync.aligned.m16n8k8.row.col.f32.tf32.tf32.f32 "
                        "{%0,%1,%2,%3},{%4,%5,%6,%7},{%8,%9},{%0,%1,%2,%3};"
                        : "+f"(acc[mt][nt][0]), "+f"(acc[mt][nt][1]),
                          "+f"(acc[mt][nt][2]), "+f"(acc[mt][nt][3])
                        : "r"(af[mt][0]), "r"(af[mt][1]), "r"(af[mt][2]), "r"(af[mt][3]),
                          "r"(bf[nt][0]), "r"(bf[nt][1]));
                }
        }
    };

    fetch(0);
    stage(0);
    __syncthreads();
    int buf = 0;
    for (int k0 = 0; k0 < Ktot; k0 += 16) {
        int nk = k0 + 16;
        if (nk < Ktot) fetch(nk);
        compute(buf);
        if (nk < Ktot) stage(buf ^ 1);
        __syncthreads();
        buf ^= 1;
    }

    // epilogue
#pragma unroll
    for (int mt = 0; mt < 4; mt++) {
        int r = row0 + wm + mt * 16 + lr;
#pragma unroll
        for (int nt = 0; nt < 4; nt++) {
            int c = col0 + wn + nt * 8 + lc * 2;
            float2 v0, v1;
            v0.x = acc[mt][nt][0] + bias[c];
            v0.y = acc[mt][nt][1] + bias[c + 1];
            v1.x = acc[mt][nt][2] + bias[c];
            v1.y = acc[mt][nt][3] + bias[c + 1];
            if (relu) {
                v0.x = fmaxf(v0.x, 0.f); v0.y = fmaxf(v0.y, 0.f);
                v1.x = fmaxf(v1.x, 0.f); v1.y = fmaxf(v1.y, 0.f);
            }
            if (r < M)     *(float2*)(out + (size_t)r * Nout + c) = v0;
            if (r + 8 < M) *(float2*)(out + (size_t)(r + 8) * Nout + c) = v1;
        }
    }
}

// ---------------- graph pooling ----------------
__global__ void k_gcount(const int* __restrict__ gid, int N) {
    int n = blockIdx.x * blockDim.x + threadIdx.x;
    unsigned act = __ballot_sync(0xffffffffu, n < N);
    if (n < N) {
        int g = gid[n];
        unsigned m = __match_any_sync(act, g);
        if ((threadIdx.x & 31) == __ffs(m) - 1) atomicAdd(&g_gcnt[g], (float)__popc(m));
    }
}

__global__ void k_pool(const int* __restrict__ gid, int N) {
    int j = threadIdx.x;          // 128 threads, one per column
    int n0 = blockIdx.x * 64;
    if (n0 >= N) return;
    int nend = min(n0 + 64, N);
    int curg = gid[n0];
    float acc = 0.f;
    for (int n = n0; n < nend; n++) {
        int g = gid[n];
        if (g != curg) {
            atomicAdd(&g_pool[curg * 128 + j], acc);
            acc = 0.f;
            curg = g;
        }
        acc += g_h3[(size_t)n * 128 + j];
    }
    atomicAdd(&g_pool[curg * 128 + j], acc);
}

// ---------------- finalize ----------------
__global__ void k_final(const float* __restrict__ wfc, const float* __restrict__ bfc,
                        float* __restrict__ out, int out_size) {
    __shared__ float emb[16 * 128];
    __shared__ float part[4];
    __shared__ float sc[16];
    int j = threadIdx.x;  // 128 threads
    for (int b = 0; b < 16; b++) {
        float c = fmaxf(g_gcnt[b], 1.0f);
        float v = g_pool[b * 128 + j] / c;
        v = (v >= 0.f) ? v : 0.01f * v;   // leaky_relu
        emb[b * 128 + j] = v;
    }
    float w = wfc[j];
    for (int b = 0; b < 16; b++) {
        float p = emb[b * 128 + j] * w;
        for (int off = 16; off; off >>= 1) p += __shfl_down_sync(0xffffffffu, p, off);
        if ((j & 31) == 0) part[j >> 5] = p;
        __syncthreads();
        if (j == 0) {
            float s = part[0] + part[1] + part[2] + part[3] + bfc[0];
            sc[b] = 1.0f / (1.0f + expf(-s));
        }
        __syncthreads();
    }
    if (out_size >= 2064) {
        if (j < 16) out[j] = sc[j];
        int base = out_size - 2048;
        for (int b = 0; b < 16; b++) out[base + b * 128 + j] = emb[b * 128 + j];
    } else if (out_size >= 2048) {
        for (int b = 0; b < 16; b++) out[b * 128 + j] = emb[b * 128 + j];
    } else {
        if (j < 16 && j < out_size) out[j] = sc[j];
    }
}

// ---------------- launch ----------------
extern "C" void kernel_launch(void* const* d_in, const int* in_sizes, int n_in,
                              void* d_out, int out_size) {
    const float* x   = (const float*)d_in[0];
    const float* Wnt = (const float*)d_in[1];
    const float* Wr1 = (const float*)d_in[2];
    const float* Ws1 = (const float*)d_in[3];
    const float* b1  = (const float*)d_in[4];
    const float* Wr2 = (const float*)d_in[5];
    const float* Ws2 = (const float*)d_in[6];
    const float* b2  = (const float*)d_in[7];
    const float* Wr3 = (const float*)d_in[8];
    const float* Ws3 = (const float*)d_in[9];
    const float* b3  = (const float*)d_in[10];
    const float* wfc = (const float*)d_in[11];
    const float* bfc = (const float*)d_in[12];
    const int* esrc  = (const int*)d_in[13];
    const int* edst  = (const int*)d_in[14];
    const int* etyp  = (const int*)d_in[15];
    const int* ntyp  = (const int*)d_in[16];
    const int* gid   = (const int*)d_in[17];
    int N = in_sizes[16];
    int E = in_sizes[13];
    int NR = N * 4;
    int NB = (NR + 1023) / 1024;

    // edge CSR build
    k_zero_i32<<<(NR + 255) / 256, 256>>>(0, NR);
    k_hist<<<(E + 255) / 256, 256>>>(edst, etyp, E);
    k_scan1<<<NB, 1024>>>(NR);
    k_scan2<<<1, 1024>>>(NB);
    k_scan3<<<NB, 1024>>>(NR);
    k_bucket<<<(E + 255) / 256, 256>>>(esrc, edst, etyp, E);

    // node-type sort + encoder GEMM
    k_zero_i32<<<1, 32>>>(1, 8);
    k_fill_nidx<<<(NIDX_CAP + 255) / 256, 256>>>();
    k_hist_nt<<<(N + 255) / 256, 256>>>(ntyp, N);
    k_nt_offsets<<<1, 32>>>();
    k_bucket_nt<<<(N + 255) / 256, 256>>>(ntyp, N);
    int gx_enc = (N + 7 * 128 + 127) / 128;
    k_enc_gemm<<<gx_enc, 256>>>(x, Wnt);

    int gagg = (N + 3) / 4;
    dim3 gh((N + 127) / 128, 2);
    dim3 go((N + 127) / 128, 1);

    // layer 1 (128 -> 256, relu)
    k_agg<128><<<gagg, 256>>>(1, N);
    k_gemm_tc<<<gh, 256>>>(Wr1, Ws1, b1, 1, N, 7, 256, 1);

    // layer 2 (256 -> 256, relu)
    k_agg<256><<<gagg, 256>>>(2, N);
    k_gemm_tc<<<gh, 256>>>(Wr2, Ws2, b2, 2, N, 8, 256, 1);

    // layer 3 (256 -> 128, no relu)
    k_agg<256><<<gagg, 256>>>(3, N);
    k_gemm_tc<<<go, 256>>>(Wr3, Ws3, b3, 3, N, 8, 128, 0);

    // pooling + head
    k_zero_pool<<<8, 256>>>();
    k_gcount<<<(N + 255) / 256, 256>>>(gid, N);
    k_pool<<<(N + 63) / 64, 128>>>(gid, N);
    k_zero_out<<<(out_size + 255) / 256, 256>>>((float*)d_out, out_size);
    k_final<<<1, 128>>>(wfc, bfc, (float*)d_out, out_size);
}